// round 2
// baseline (speedup 1.0000x reference)
#include <cuda_runtime.h>
#include <math.h>

#define NN   50000
#define NE   800000
#define ET   (NE + NN)     // edges + self loops
#define FIN  42
#define HIDD 128

// ---------------- scratch (device globals; no allocation allowed) -------------
__device__ float g_xn [NN * FIN];
__device__ float g_h  [NN * HIDD];
__device__ float g_cur[NN * HIDD];
__device__ float g_hs [NN];
__device__ float g_hd [NN];
__device__ int   g_deg [NN];
__device__ int   g_off [NN + 1];
__device__ int   g_fill[NN];
__device__ int   g_csr [ET];

// ---------------- L1 normalize input ----------------
__global__ void k_xn(const float* __restrict__ x) {
    int w = (blockIdx.x * blockDim.x + threadIdx.x) >> 5;
    int lane = threadIdx.x & 31;
    if (w >= NN) return;
    float s = 0.f;
    for (int j = lane; j < FIN; j += 32) s += fabsf(x[w * FIN + j]);
    #pragma unroll
    for (int o = 16; o; o >>= 1) s += __shfl_xor_sync(0xffffffff, s, o);
    float inv = 1.f / fmaxf(s, 1e-12f);
    for (int j = lane; j < FIN; j += 32) g_xn[w * FIN + j] = x[w * FIN + j] * inv;
}

// ---------------- CSR build (by destination) ----------------
__global__ void k_zero_deg() {
    int i = blockIdx.x * blockDim.x + threadIdx.x;
    if (i < NN) g_deg[i] = 0;
}

__global__ void k_count(const int* __restrict__ ei) {
    int e = blockIdx.x * blockDim.x + threadIdx.x;
    if (e >= ET) return;
    int dst = (e < NE) ? ei[NE + e] : (e - NE);
    atomicAdd(&g_deg[dst], 1);
}

__global__ void k_scan() {   // single block, 1024 threads
    __shared__ int part[1024];
    const int CH = (NN + 1023) / 1024;   // 49
    int t = threadIdx.x;
    int lo = t * CH, hi = min(lo + CH, NN);
    int s = 0;
    for (int i = lo; i < hi; i++) s += g_deg[i];
    part[t] = s;
    __syncthreads();
    for (int off = 1; off < 1024; off <<= 1) {
        int v = (t >= off) ? part[t - off] : 0;
        __syncthreads();
        part[t] += v;
        __syncthreads();
    }
    int run = (t == 0) ? 0 : part[t - 1];
    for (int i = lo; i < hi; i++) {
        g_off[i] = run;
        g_fill[i] = run;
        run += g_deg[i];
    }
    if (t == 1023) g_off[NN] = part[1023];
}

__global__ void k_scatter(const int* __restrict__ ei) {
    int e = blockIdx.x * blockDim.x + threadIdx.x;
    if (e >= ET) return;
    int src, dst;
    if (e < NE) { src = ei[e]; dst = ei[NE + e]; }
    else        { src = e - NE; dst = e - NE; }
    int pos = atomicAdd(&g_fill[dst], 1);
    g_csr[pos] = src;
}

// ---------------- SGEMM: C[M,N] = A[M,K] @ B[K,N], N <= 128 ----------------
__global__ void __launch_bounds__(256) k_sgemm(
    const float* __restrict__ A, const float* __restrict__ B,
    float* __restrict__ C, int M, int N, int K)
{
    __shared__ float As[8][128];
    __shared__ float Bs[8][128];
    int tid = threadIdx.x;
    int row0 = blockIdx.x * 128;
    int tr = tid >> 4;        // 0..15
    int tc = tid & 15;        // 0..15
    float acc[8][8];
    #pragma unroll
    for (int i = 0; i < 8; i++)
        #pragma unroll
        for (int j = 0; j < 8; j++) acc[i][j] = 0.f;

    for (int k0 = 0; k0 < K; k0 += 8) {
        #pragma unroll
        for (int l = 0; l < 4; l++) {
            int idx = tid + l * 256;           // 0..1023
            int k = idx & 7, m = idx >> 3;
            int gr = row0 + m, gk = k0 + k;
            As[k][m] = (gr < M && gk < K) ? A[gr * K + gk] : 0.f;
        }
        #pragma unroll
        for (int l = 0; l < 4; l++) {
            int idx = tid + l * 256;
            int n = idx & 127, k = idx >> 7;
            int gk = k0 + k;
            Bs[k][n] = (gk < K && n < N) ? B[gk * N + n] : 0.f;
        }
        __syncthreads();
        #pragma unroll
        for (int kk = 0; kk < 8; kk++) {
            float ar[8], br[8];
            #pragma unroll
            for (int i = 0; i < 8; i++) ar[i] = As[kk][tr * 8 + i];
            #pragma unroll
            for (int j = 0; j < 8; j++) br[j] = Bs[kk][tc * 8 + j];
            #pragma unroll
            for (int i = 0; i < 8; i++)
                #pragma unroll
                for (int j = 0; j < 8; j++) acc[i][j] += ar[i] * br[j];
        }
        __syncthreads();
    }
    #pragma unroll
    for (int i = 0; i < 8; i++) {
        int r = row0 + tr * 8 + i;
        if (r >= M) continue;
        #pragma unroll
        for (int j = 0; j < 8; j++) {
            int c = tc * 8 + j;
            if (c < N) C[r * N + c] = acc[i][j];
        }
    }
}

// ---------------- per-node attention dot products ----------------
__global__ void k_dots(const float* __restrict__ h,
                       const float* __restrict__ as_, const float* __restrict__ ad_,
                       int F) {
    int w = (blockIdx.x * blockDim.x + threadIdx.x) >> 5;
    int lane = threadIdx.x & 31;
    if (w >= NN) return;
    float s = 0.f, d = 0.f;
    for (int j = lane; j < F; j += 32) {
        float v = h[w * F + j];
        s += v * as_[j];
        d += v * ad_[j];
    }
    #pragma unroll
    for (int o = 16; o; o >>= 1) {
        s += __shfl_xor_sync(0xffffffff, s, o);
        d += __shfl_xor_sync(0xffffffff, d, o);
    }
    if (lane == 0) { g_hs[w] = s; g_hd[w] = d; }
}

// ---------------- softmax-attention aggregation: block per dst node ----------
__global__ void __launch_bounds__(128) k_agg(
    const float* __restrict__ h, const float* __restrict__ bias,
    float* __restrict__ out, int F)
{
    int node = blockIdx.x;
    int t = threadIdx.x;  // 128
    int lane = t & 31, warp = t >> 5;
    __shared__ float sh_w[128];
    __shared__ int   sh_src[128];
    __shared__ float wred[4];
    int beg = g_off[node], end = g_off[node + 1];
    float hdv = g_hd[node];
    float M = -INFINITY, S = 0.f, acc = 0.f;

    for (int c0 = beg; c0 < end; c0 += 128) {
        int i = c0 + t;
        float e = -INFINITY;
        int sidx = 0;
        if (i < end) {
            sidx = g_csr[i];
            float s = g_hs[sidx] + hdv;
            e = (s > 0.f) ? s : 0.2f * s;   // leaky_relu 0.2
        }
        sh_src[t] = sidx;
        // chunk max: warp shuffle reduce, then 4-value exchange
        float wm = e;
        #pragma unroll
        for (int o = 16; o; o >>= 1) wm = fmaxf(wm, __shfl_xor_sync(0xffffffff, wm, o));
        if (lane == 0) wred[warp] = wm;
        __syncthreads();
        float cmax = fmaxf(fmaxf(wred[0], wred[1]), fmaxf(wred[2], wred[3]));
        float newM = fmaxf(M, cmax);
        float w = (i < end) ? expf(e - newM) : 0.f;
        sh_w[t] = w;
        __syncthreads();
        float scale = expf(M - newM);   // 0 on first chunk (M = -inf)
        S *= scale;
        acc *= scale;
        int cnt = min(128, end - c0);
        for (int k = 0; k < cnt; k++) {
            float wk = sh_w[k];
            S += wk;
            if (t < F) acc += wk * h[sh_src[k] * F + t];
        }
        M = newM;
        __syncthreads();
    }
    if (t < F) out[node * F + t] = tanhf(acc / (S + 1e-16f) + bias[t]);
}

// ---------------- mask MLP + soft-argmax gating (32 nodes per block) ---------
__global__ void __launch_bounds__(128) k_mask(
    float* __restrict__ cur,
    const float* __restrict__ mw1, const float* __restrict__ mb1,
    const float* __restrict__ mw2, const float* __restrict__ mb2,
    const float* __restrict__ mw3, const float* __restrict__ mb3,
    const float* __restrict__ mw4, const float* __restrict__ mb4)
{
    __shared__ float w1[128 * 64];
    __shared__ float w2[64 * 16];
    __shared__ float w3[16 * 16];
    __shared__ float w4[16 * 2];
    __shared__ float bb1[64], bb2[16], bb3[16], bb4[2];
    __shared__ float lat[128], m1[64], m2[16], m3[16];
    __shared__ float sa;
    int t = threadIdx.x;
    for (int i = t; i < 128 * 64; i += 128) w1[i] = mw1[i];
    for (int i = t; i < 64 * 16;  i += 128) w2[i] = mw2[i];
    for (int i = t; i < 16 * 16;  i += 128) w3[i] = mw3[i];
    if (t < 32) w4[t] = mw4[t];
    if (t < 64) bb1[t] = mb1[t];
    if (t < 16) { bb2[t] = mb2[t]; bb3[t] = mb3[t]; }
    if (t < 2)  bb4[t] = mb4[t];
    __syncthreads();

    int n0 = blockIdx.x * 32;
    int n1 = min(n0 + 32, NN);
    for (int n = n0; n < n1; n++) {
        lat[t] = cur[n * 128 + t];
        __syncthreads();
        if (t < 64) {
            float s = bb1[t];
            #pragma unroll 8
            for (int k = 0; k < 128; k++) s += lat[k] * w1[k * 64 + t];
            m1[t] = tanhf(s);
        }
        __syncthreads();
        if (t < 16) {
            float s = bb2[t];
            #pragma unroll
            for (int k = 0; k < 64; k++) s += m1[k] * w2[k * 16 + t];
            m2[t] = tanhf(s);
        }
        __syncthreads();
        if (t < 16) {
            float s = bb3[t];
            #pragma unroll
            for (int k = 0; k < 16; k++) s += m2[k] * w3[k * 16 + t];
            m3[t] = tanhf(s);
        }
        __syncthreads();
        if (t == 0) {
            float o0 = bb4[0], o1 = bb4[1];
            #pragma unroll
            for (int k = 0; k < 16; k++) {
                o0 += m3[k] * w4[k * 2];
                o1 += m3[k] * w4[k * 2 + 1];
            }
            float mx = fmaxf(o0, o1);
            float e0 = expf(o0 - mx), e1 = expf(o1 - mx);
            sa = e1 / (e0 + e1);           // soft argmax = p(class 1)
        }
        __syncthreads();
        cur[n * 128 + t] = lat[t] * sa;
    }
}

// ---------------- orchestration ----------------
extern "C" void kernel_launch(void* const* d_in, const int* in_sizes, int n_in,
                              void* d_out, int out_size)
{
    const float* x   = (const float*)d_in[0];
    const int*   ei  = (const int*)  d_in[1];
    // d_in[2] = batch (unused), d_in[3] = epoch (unused)
    const float* W1  = (const float*)d_in[4];
    const float* a1s = (const float*)d_in[5];
    const float* a1d = (const float*)d_in[6];
    const float* b1  = (const float*)d_in[7];
    const float* Wm  = (const float*)d_in[8];
    const float* ams = (const float*)d_in[9];
    const float* amd = (const float*)d_in[10];
    const float* bm  = (const float*)d_in[11];
    const float* W8  = (const float*)d_in[12];
    const float* a8s = (const float*)d_in[13];
    const float* a8d = (const float*)d_in[14];
    const float* b8  = (const float*)d_in[15];
    const float* mw1 = (const float*)d_in[16];
    const float* mb1 = (const float*)d_in[17];
    const float* mw2 = (const float*)d_in[18];
    const float* mb2 = (const float*)d_in[19];
    const float* mw3 = (const float*)d_in[20];
    const float* mb3 = (const float*)d_in[21];
    const float* mw4 = (const float*)d_in[22];
    const float* mb4 = (const float*)d_in[23];
    float* outp = (float*)d_out;

    void *pv;
    cudaGetSymbolAddress(&pv, g_xn);   float* p_xn  = (float*)pv;
    cudaGetSymbolAddress(&pv, g_h);    float* p_h   = (float*)pv;
    cudaGetSymbolAddress(&pv, g_cur);  float* p_cur = (float*)pv;

    const int EB = (ET + 255) / 256;
    const int GEMM_B = (NN + 127) / 128;   // 391
    const int WARP8  = (NN + 7) / 8;       // 6250 blocks of 8 warps

    // input normalize + CSR build
    k_xn<<<WARP8, 256>>>(x);
    k_zero_deg<<<(NN + 255) / 256, 256>>>();
    k_count<<<EB, 256>>>(ei);
    k_scan<<<1, 1024>>>();
    k_scatter<<<EB, 256>>>(ei);

    // conv1: 42 -> 128
    k_sgemm<<<GEMM_B, 256>>>(p_xn, W1, p_h, NN, HIDD, FIN);
    k_dots<<<WARP8, 256>>>(p_h, a1s, a1d, HIDD);
    k_agg<<<NN, 128>>>(p_h, b1, p_cur, HIDD);

    // conv2..conv4
    for (int i = 0; i < 3; i++) {
        k_sgemm<<<GEMM_B, 256>>>(p_cur, Wm + i * HIDD * HIDD, p_h, NN, HIDD, HIDD);
        k_dots<<<WARP8, 256>>>(p_h, ams + i * HIDD, amd + i * HIDD, HIDD);
        k_agg<<<NN, 128>>>(p_h, bm + i * HIDD, p_cur, HIDD);
    }

    // mask MLP gating (in place on latent)
    k_mask<<<(NN + 31) / 32, 128>>>(p_cur, mw1, mb1, mw2, mb2, mw3, mb3, mw4, mb4);

    // conv5..conv7
    for (int i = 3; i < 6; i++) {
        k_sgemm<<<GEMM_B, 256>>>(p_cur, Wm + i * HIDD * HIDD, p_h, NN, HIDD, HIDD);
        k_dots<<<WARP8, 256>>>(p_h, ams + i * HIDD, amd + i * HIDD, HIDD);
        k_agg<<<NN, 128>>>(p_h, bm + i * HIDD, p_cur, HIDD);
    }

    // conv8: 128 -> 42, writes final output
    k_sgemm<<<GEMM_B, 256>>>(p_cur, W8, p_h, NN, FIN, HIDD);
    k_dots<<<WARP8, 256>>>(p_h, a8s, a8d, FIN);
    k_agg<<<NN, 128>>>(p_h, b8, outp, FIN);
}